// round 7
// baseline (speedup 1.0000x reference)
#include <cuda_runtime.h>
#include <cuda_fp16.h>
#include <cstdint>
#include <math.h>

#define BSZ    64
#define FDIM   256
#define MDIM   128
#define NPAIRS 2080            // 64*65/2 triangular pairs
#define KC     32              // K per chunk
#define NCH    (FDIM / KC)     // 8
#define TILE_B 8192            // 128 rows x 64B (32 fp16)
#define STAGE_B (4 * TILE_B)   // Ah, Al, Bh, Bl = 32KB
#define STAGES 3
#define LO_OFF (BSZ * MDIM * FDIM)   // elements between hi and lo planes
typedef unsigned long long ull;

// fp16 split scratch: [tensor][hi/lo][b][m][f], f contiguous = 16 MB
__device__ __align__(16) __half XS[2][2][BSZ][MDIM][FDIM];

// ---------------- pre-pass: transpose + fp16 hi/lo split ----------------
__global__ void split_transpose(const float* __restrict__ m1,
                                const float* __restrict__ m2) {
    __shared__ float tile[32][33];
    const int b  = blockIdx.x;
    const int f0 = blockIdx.y * 32;
    const int mt = blockIdx.z & 3, t = blockIdx.z >> 2;
    const int m0 = mt * 32;
    const float* src = t ? m2 : m1;
    const int tx = threadIdx.x, ty = threadIdx.y;
    #pragma unroll
    for (int i = 0; i < 4; i++) {
        int f = f0 + ty + i * 8;
        tile[ty + i * 8][tx] = src[((size_t)b * FDIM + f) * MDIM + m0 + tx];
    }
    __syncthreads();
    #pragma unroll
    for (int i = 0; i < 4; i++) {
        int m = m0 + ty + i * 8;
        int f = f0 + tx;
        float v = tile[tx][ty + i * 8];
        __half hi = __float2half_rn(v);
        __half lo = __float2half_rn(v - __half2float(hi));
        XS[t][0][b][m][f] = hi;
        XS[t][1][b][m][f] = lo;
    }
}

// ---------------- helpers ----------------
__device__ __forceinline__ uint32_t s2u(const void* p) {
    uint32_t a;
    asm("{ .reg .u64 t; cvta.to.shared.u64 t, %1; cvt.u32.u64 %0, t; }"
        : "=r"(a) : "l"(p));
    return a;
}
__device__ __forceinline__ void cpasync16(uint32_t dst, const void* src) {
    asm volatile("cp.async.cg.shared.global [%0], [%1], 16;"
                 :: "r"(dst), "l"(src));
}
template <int N>
__device__ __forceinline__ void cp_wait() {
    asm volatile("cp.async.wait_group %0;" :: "n"(N) : "memory");
}
__device__ __forceinline__ void ldsm4(uint32_t* r, uint32_t addr) {
    asm volatile("ldmatrix.sync.aligned.m8n8.x4.shared.b16 {%0,%1,%2,%3}, [%4];"
                 : "=r"(r[0]), "=r"(r[1]), "=r"(r[2]), "=r"(r[3]) : "r"(addr));
}
// f32-accumulator HMMA
__device__ __forceinline__ void mma_f32(float* c, const uint32_t* a,
                                        const uint32_t* b) {
    asm volatile(
        "mma.sync.aligned.m16n8k16.row.col.f32.f16.f16.f32 "
        "{%0,%1,%2,%3}, {%4,%5,%6,%7}, {%8,%9}, {%0,%1,%2,%3};"
        : "+f"(c[0]), "+f"(c[1]), "+f"(c[2]), "+f"(c[3])
        : "r"(a[0]), "r"(a[1]), "r"(a[2]), "r"(a[3]), "r"(b[0]), "r"(b[1]));
}
// f16-accumulator HMMA (correction terms, packed f16x2 in 2 regs)
__device__ __forceinline__ void mma_f16(uint32_t* c, const uint32_t* a,
                                        const uint32_t* b) {
    asm volatile(
        "mma.sync.aligned.m16n8k16.row.col.f16.f16.f16.f16 "
        "{%0,%1}, {%2,%3,%4,%5}, {%6,%7}, {%0,%1};"
        : "+r"(c[0]), "+r"(c[1])
        : "r"(a[0]), "r"(a[1]), "r"(a[2]), "r"(a[3]), "r"(b[0]), "r"(b[1]));
}
// swizzled byte offset of (row r, 16B-chunk j) inside a [128][64B] tile
__device__ __forceinline__ uint32_t swz(int r, int j) {
    return (uint32_t)(r * 64 + ((j ^ ((r >> 1) & 3)) << 4));
}

// ---------------- main kernel ----------------
__global__ __launch_bounds__(512, 2)
void pair_hmma(float* __restrict__ out) {
    extern __shared__ char dsm[];
    __shared__ float s_mn[16], s_mx[16];
    __shared__ ull   s_h[16][2];

    const int tid  = threadIdx.x;
    const int lane = tid & 31;
    const int wid  = tid >> 5;          // 0..15
    const int t    = blockIdx.y;

    // decode triangular pair p -> (a, b), a <= b
    int p = blockIdx.x;
    int b = (int)floorf((sqrtf(8.0f * (float)p + 1.0f) - 1.0f) * 0.5f);
    while ((b + 1) * (b + 2) / 2 <= p) ++b;
    while (b * (b + 1) / 2 > p) --b;
    const int a = p - b * (b + 1) / 2;

    const uint32_t sbase = s2u(dsm);
    const int m_base = (wid >> 2) * 32;
    const int n_base = (wid & 3) * 32;

    // hoisted ldmatrix offsets (chunk-invariant): [mt/t2][ks]
    uint32_t off_a[2][2], off_b[2][2];
    #pragma unroll
    for (int ks = 0; ks < 2; ks++) {
        #pragma unroll
        for (int mt = 0; mt < 2; mt++)
            off_a[mt][ks] = swz(m_base + mt * 16 + (lane & 15),
                                ks * 2 + (lane >> 4));
        #pragma unroll
        for (int t2 = 0; t2 < 2; t2++)
            off_b[t2][ks] = swz(n_base + t2 * 16 + ((lane >> 4) << 3) + (lane & 7),
                                ks * 2 + ((lane >> 3) & 1));
    }

    float    accF[2][4][4];   // hh term, fp32
    uint32_t accH[2][4][2];   // hl+lh corrections, packed f16x2
    #pragma unroll
    for (int i = 0; i < 2; i++)
        #pragma unroll
        for (int j = 0; j < 4; j++) {
            #pragma unroll
            for (int k = 0; k < 4; k++) accF[i][j][k] = 0.0f;
            accH[i][j][0] = 0u; accH[i][j][1] = 0u;
        }

    // --- per-thread fixed cp.async slot ---
    const int pr = tid >> 2;            // 0..127
    const int pj = tid & 3;             // 0..3
    const uint32_t pdst = swz(pr, pj);
    const __half* pAh = &XS[t][0][a][pr][pj * 8];
    const long dB = (long)(b - a) * (MDIM * FDIM);   // hi(a) -> hi(b)

    auto prefetch = [&](int ch) {
        const uint32_t stg = sbase + (uint32_t)(ch % STAGES) * STAGE_B;
        const __half* base = pAh + ch * KC;
        cpasync16(stg + pdst,              base);
        cpasync16(stg + TILE_B + pdst,     base + LO_OFF);
        cpasync16(stg + 2 * TILE_B + pdst, base + dB);
        cpasync16(stg + 3 * TILE_B + pdst, base + dB + LO_OFF);
        asm volatile("cp.async.commit_group;" ::: "memory");
    };

    prefetch(0);
    prefetch(1);

    #pragma unroll
    for (int ch = 0; ch < NCH; ch++) {
        if (ch < NCH - 1) cp_wait<1>(); else cp_wait<0>();
        __syncthreads();
        if (ch + 2 < NCH) prefetch(ch + 2);

        const uint32_t aH = sbase + (uint32_t)(ch % STAGES) * STAGE_B;
        const uint32_t aL = aH + TILE_B;
        const uint32_t bH = aH + 2 * TILE_B;
        const uint32_t bL = aH + 3 * TILE_B;

        #pragma unroll
        for (int ks = 0; ks < 2; ks++) {
            uint32_t av[2][4];
            // ---- P1: hh (fp32 acc) ----
            ldsm4(av[0], aH + off_a[0][ks]);
            ldsm4(av[1], aH + off_a[1][ks]);
            #pragma unroll
            for (int t2 = 0; t2 < 2; t2++) {
                uint32_t bq[4];
                ldsm4(bq, bH + off_b[t2][ks]);
                #pragma unroll
                for (int mt = 0; mt < 2; mt++) {
                    mma_f32(accF[mt][t2 * 2],     av[mt], bq);
                    mma_f32(accF[mt][t2 * 2 + 1], av[mt], bq + 2);
                }
            }
            // ---- P2: Ah * Bl (f16 acc), A regs still hold hi ----
            #pragma unroll
            for (int t2 = 0; t2 < 2; t2++) {
                uint32_t bq[4];
                ldsm4(bq, bL + off_b[t2][ks]);
                #pragma unroll
                for (int mt = 0; mt < 2; mt++) {
                    mma_f16(accH[mt][t2 * 2],     av[mt], bq);
                    mma_f16(accH[mt][t2 * 2 + 1], av[mt], bq + 2);
                }
            }
            // ---- P3: Al * Bh (f16 acc), reload A as lo ----
            ldsm4(av[0], aL + off_a[0][ks]);
            ldsm4(av[1], aL + off_a[1][ks]);
            #pragma unroll
            for (int t2 = 0; t2 < 2; t2++) {
                uint32_t bq[4];
                ldsm4(bq, bH + off_b[t2][ks]);
                #pragma unroll
                for (int mt = 0; mt < 2; mt++) {
                    mma_f16(accH[mt][t2 * 2],     av[mt], bq);
                    mma_f16(accH[mt][t2 * 2 + 1], av[mt], bq + 2);
                }
            }
        }
    }

    // -------- epilogue: combine, min/max + histogram over 16384 values ------
    float v[32];
    #pragma unroll
    for (int mt = 0; mt < 2; mt++)
        #pragma unroll
        for (int nt = 0; nt < 4; nt++) {
            const int base = (mt * 4 + nt) * 4;
            float2 c01 = __half22float2(*(const __half2*)&accH[mt][nt][0]);
            float2 c23 = __half22float2(*(const __half2*)&accH[mt][nt][1]);
            v[base + 0] = accF[mt][nt][0] + c01.x;
            v[base + 1] = accF[mt][nt][1] + c01.y;
            v[base + 2] = accF[mt][nt][2] + c23.x;
            v[base + 3] = accF[mt][nt][3] + c23.y;
        }

    float mn = v[0], mx = v[0];
    #pragma unroll
    for (int q = 1; q < 32; q++) { mn = fminf(mn, v[q]); mx = fmaxf(mx, v[q]); }
    #pragma unroll
    for (int o = 16; o > 0; o >>= 1) {
        mn = fminf(mn, __shfl_xor_sync(0xffffffffu, mn, o));
        mx = fmaxf(mx, __shfl_xor_sync(0xffffffffu, mx, o));
    }
    if (lane == 0) { s_mn[wid] = mn; s_mx[wid] = mx; }
    __syncthreads();
    mn = s_mn[0]; mx = s_mx[0];
    #pragma unroll
    for (int w = 1; w < 16; w++) {
        mn = fminf(mn, s_mn[w]); mx = fmaxf(mx, s_mx[w]);
    }
    const float denom = (mx > mn) ? (mx - mn) : 1.0f;

    ull h0 = 0ull, h1 = 0ull;
    #pragma unroll
    for (int q = 0; q < 32; q++) {
        const float tt = (v[q] - mn) / denom * 8.0f;
        int bi = (int)tt;
        if (bi > 7) bi = 7;
        const ull one = 1ull << ((bi & 3) << 4);
        if (bi < 4) h0 += one; else h1 += one;
    }
    #pragma unroll
    for (int o = 16; o > 0; o >>= 1) {
        h0 += __shfl_xor_sync(0xffffffffu, h0, o);
        h1 += __shfl_xor_sync(0xffffffffu, h1, o);
    }
    if (lane == 0) { s_h[wid][0] = h0; s_h[wid][1] = h1; }
    __syncthreads();

    if (tid == 0) {
        ull H0 = 0ull, H1 = 0ull;
        #pragma unroll
        for (int w = 0; w < 16; w++) { H0 += s_h[w][0]; H1 += s_h[w][1]; }
        float c[8];
        #pragma unroll
        for (int bn = 0; bn < 4; bn++) {
            c[bn]     = (float)((H0 >> (bn * 16)) & 0xFFFFull);
            c[bn + 4] = (float)((H1 >> (bn * 16)) & 0xFFFFull);
        }
        float ss = 0.0f;
        #pragma unroll
        for (int bn = 0; bn < 8; bn++) ss += c[bn] * c[bn];
        float nrm = fmaxf(sqrtf(ss), 1e-12f);
        float* o1 = out + (a * BSZ + b) * 16 + t * 8;
        float* o2 = out + (b * BSZ + a) * 16 + t * 8;
        #pragma unroll
        for (int bn = 0; bn < 8; bn++) {
            const float val = c[bn] / nrm;
            o1[bn] = val;
            o2[bn] = val;   // hist(a,b) == hist(b,a) by symmetry
        }
    }
}

extern "C" void kernel_launch(void* const* d_in, const int* in_sizes, int n_in,
                              void* d_out, int out_size) {
    const float* m1 = (const float*)d_in[0];
    const float* m2 = (const float*)d_in[1];
    float* out = (float*)d_out;

    split_transpose<<<dim3(BSZ, 8, 8), dim3(32, 8)>>>(m1, m2);

    cudaFuncSetAttribute(pair_hmma,
                         cudaFuncAttributeMaxDynamicSharedMemorySize,
                         STAGES * STAGE_B);
    pair_hmma<<<dim3(NPAIRS, 2), 512, STAGES * STAGE_B>>>(out);
}

// round 8
// speedup vs baseline: 1.1737x; 1.1737x over previous
#include <cuda_runtime.h>
#include <cuda_fp16.h>
#include <cstdint>
#include <math.h>

#define BSZ    64
#define FDIM   256
#define MDIM   128
#define NPAIRS 2080            // 64*65/2 triangular pairs
#define NTASK  (2 * NPAIRS)    // 4160 (pair, tensor) tasks
#define GRID   296             // 148 SMs x 2 CTAs, persistent
#define KC     32              // K per chunk
#define NCH    (FDIM / KC)     // 8
#define TILE_B 8192            // 128 rows x 64B (32 fp16)
#define STAGE_B (4 * TILE_B)   // Ah, Al, Bh, Bl = 32KB
#define STAGES 3
#define LO_OFF (BSZ * MDIM * FDIM)   // elements between hi and lo planes
typedef unsigned long long ull;

// fp16 split scratch: [tensor][hi/lo][b][m][f], f contiguous = 16 MB
__device__ __align__(16) __half XS[2][2][BSZ][MDIM][FDIM];

// ---------------- pre-pass: transpose + fp16 hi/lo split ----------------
__global__ void split_transpose(const float* __restrict__ m1,
                                const float* __restrict__ m2) {
    __shared__ float tile[32][33];
    const int b  = blockIdx.x;
    const int f0 = blockIdx.y * 32;
    const int mt = blockIdx.z & 3, t = blockIdx.z >> 2;
    const int m0 = mt * 32;
    const float* src = t ? m2 : m1;
    const int tx = threadIdx.x, ty = threadIdx.y;
    #pragma unroll
    for (int i = 0; i < 4; i++) {
        int f = f0 + ty + i * 8;
        tile[ty + i * 8][tx] = src[((size_t)b * FDIM + f) * MDIM + m0 + tx];
    }
    __syncthreads();
    #pragma unroll
    for (int i = 0; i < 4; i++) {
        int m = m0 + ty + i * 8;
        int f = f0 + tx;
        float v = tile[tx][ty + i * 8];
        __half hi = __float2half_rn(v);
        __half lo = __float2half_rn(v - __half2float(hi));
        XS[t][0][b][m][f] = hi;
        XS[t][1][b][m][f] = lo;
    }
}

// ---------------- helpers ----------------
__device__ __forceinline__ uint32_t s2u(const void* p) {
    uint32_t a;
    asm("{ .reg .u64 t; cvta.to.shared.u64 t, %1; cvt.u32.u64 %0, t; }"
        : "=r"(a) : "l"(p));
    return a;
}
__device__ __forceinline__ void cpasync16(uint32_t dst, const void* src) {
    asm volatile("cp.async.cg.shared.global [%0], [%1], 16;"
                 :: "r"(dst), "l"(src));
}
template <int N>
__device__ __forceinline__ void cp_wait() {
    asm volatile("cp.async.wait_group %0;" :: "n"(N) : "memory");
}
__device__ __forceinline__ void ldsm4(uint32_t* r, uint32_t addr) {
    asm volatile("ldmatrix.sync.aligned.m8n8.x4.shared.b16 {%0,%1,%2,%3}, [%4];"
                 : "=r"(r[0]), "=r"(r[1]), "=r"(r[2]), "=r"(r[3]) : "r"(addr));
}
__device__ __forceinline__ void mma16816(float* c, const uint32_t* a,
                                         const uint32_t* b) {
    asm volatile(
        "mma.sync.aligned.m16n8k16.row.col.f32.f16.f16.f32 "
        "{%0,%1,%2,%3}, {%4,%5,%6,%7}, {%8,%9}, {%0,%1,%2,%3};"
        : "+f"(c[0]), "+f"(c[1]), "+f"(c[2]), "+f"(c[3])
        : "r"(a[0]), "r"(a[1]), "r"(a[2]), "r"(a[3]), "r"(b[0]), "r"(b[1]));
}
// swizzled byte offset of (row r, 16B-chunk j) inside a [128][64B] tile
__device__ __forceinline__ uint32_t swz(int r, int j) {
    return (uint32_t)(r * 64 + ((j ^ ((r >> 1) & 3)) << 4));
}
// decode task -> (t, a, b) with a <= b
__device__ __forceinline__ void decode_task(int task, int& t, int& a, int& b) {
    int p = task;
    t = 0;
    if (p >= NPAIRS) { t = 1; p -= NPAIRS; }
    b = (int)floorf((sqrtf(8.0f * (float)p + 1.0f) - 1.0f) * 0.5f);
    while ((b + 1) * (b + 2) / 2 <= p) ++b;
    while (b * (b + 1) / 2 > p) --b;
    a = p - b * (b + 1) / 2;
}

// ---------------- persistent main kernel ----------------
__global__ __launch_bounds__(512, 2)
void pair_hmma(float* __restrict__ out) {
    extern __shared__ char dsm[];
    __shared__ float s_mn[16], s_mx[16];
    __shared__ ull   s_h[16][2];

    const int tid  = threadIdx.x;
    const int lane = tid & 31;
    const int wid  = tid >> 5;          // 0..15
    const int cta  = blockIdx.x;

    const uint32_t sbase = s2u(dsm);
    const int m_base = (wid >> 2) * 32;
    const int n_base = (wid & 3) * 32;

    // per-thread fixed cp.async slot
    const int pr = tid >> 2;            // 0..127
    const int pj = tid & 3;             // 0..3
    const uint32_t pdst = swz(pr, pj);

    const int nk = (NTASK - cta + GRID - 1) / GRID;  // tasks for this CTA
    const int total_ch = nk * 8;

    // prefetch global-chunk q (task = cta + (q/8)*GRID, chunk = q%8)
    // into ring stage given by byte offset stg.
    auto prefetch = [&](int q, uint32_t stg) {
        const int k  = q >> 3;
        const int ch = q & 7;
        int t, a, b;
        decode_task(cta + k * GRID, t, a, b);
        const __half* base = &XS[t][0][a][pr][pj * 8] + ch * KC;
        const long dB = (long)(b - a) * (MDIM * FDIM);
        cpasync16(stg + pdst,              base);
        cpasync16(stg + TILE_B + pdst,     base + LO_OFF);
        cpasync16(stg + 2 * TILE_B + pdst, base + dB);
        cpasync16(stg + 3 * TILE_B + pdst, base + dB + LO_OFF);
        asm volatile("cp.async.commit_group;" ::: "memory");
    };

    prefetch(0, sbase);
    prefetch(1, sbase + STAGE_B);
    uint32_t prodS = sbase + 2 * STAGE_B;   // stage for next prefetch
    uint32_t consS = sbase;                 // stage consumed this chunk
    int q = 0;

    for (int k = 0; k < nk; k++) {
        int t, a, b;
        decode_task(cta + k * GRID, t, a, b);

        float acc[2][4][4];
        #pragma unroll
        for (int i = 0; i < 2; i++)
            #pragma unroll
            for (int j = 0; j < 4; j++)
                #pragma unroll
                for (int c2 = 0; c2 < 4; c2++) acc[i][j][c2] = 0.0f;

        #pragma unroll
        for (int ch = 0; ch < NCH; ch++) {
            if (q == total_ch - 1) cp_wait<0>(); else cp_wait<1>();
            __syncthreads();
            if (q + 2 < total_ch) {
                prefetch(q + 2, prodS);
                prodS += STAGE_B;
                if (prodS == sbase + 3 * STAGE_B) prodS = sbase;
            }

            const uint32_t aH = consS;
            const uint32_t aL = aH + TILE_B;
            const uint32_t bH = aH + 2 * TILE_B;
            const uint32_t bL = aH + 3 * TILE_B;
            consS += STAGE_B;
            if (consS == sbase + 3 * STAGE_B) consS = sbase;
            q++;

            #pragma unroll
            for (int ks = 0; ks < 2; ks++) {
                uint32_t ah[2][4], al[2][4];
                #pragma unroll
                for (int mt = 0; mt < 2; mt++) {
                    const uint32_t off = swz(m_base + mt * 16 + (lane & 15),
                                             ks * 2 + (lane >> 4));
                    ldsm4(ah[mt], aH + off);
                    ldsm4(al[mt], aL + off);
                }
                #pragma unroll
                for (int t2 = 0; t2 < 2; t2++) {
                    uint32_t bh[4], bl[4];
                    const uint32_t off = swz(n_base + t2 * 16 +
                                             ((lane >> 4) << 3) + (lane & 7),
                                             ks * 2 + ((lane >> 3) & 1));
                    ldsm4(bh, bH + off);
                    ldsm4(bl, bL + off);
                    #pragma unroll
                    for (int mt = 0; mt < 2; mt++)
                        #pragma unroll
                        for (int n2 = 0; n2 < 2; n2++) {
                            float* c = acc[mt][t2 * 2 + n2];
                            mma16816(c, ah[mt], &bh[n2 * 2]);
                            mma16816(c, ah[mt], &bl[n2 * 2]);
                            mma16816(c, al[mt], &bh[n2 * 2]);
                        }
                }
            }
        }

        // ---- epilogue: min/max + histogram over 16384 CTA values ----
        const float* va = &acc[0][0][0];
        float mn = va[0], mx = va[0];
        #pragma unroll
        for (int qq = 1; qq < 32; qq++) {
            mn = fminf(mn, va[qq]); mx = fmaxf(mx, va[qq]);
        }
        #pragma unroll
        for (int o = 16; o > 0; o >>= 1) {
            mn = fminf(mn, __shfl_xor_sync(0xffffffffu, mn, o));
            mx = fmaxf(mx, __shfl_xor_sync(0xffffffffu, mx, o));
        }
        if (lane == 0) { s_mn[wid] = mn; s_mx[wid] = mx; }
        __syncthreads();
        mn = s_mn[0]; mx = s_mx[0];
        #pragma unroll
        for (int w = 1; w < 16; w++) {
            mn = fminf(mn, s_mn[w]); mx = fmaxf(mx, s_mx[w]);
        }
        const float denom = (mx > mn) ? (mx - mn) : 1.0f;

        ull h0 = 0ull, h1 = 0ull;
        #pragma unroll
        for (int qq = 0; qq < 32; qq++) {
            const float tt = (va[qq] - mn) / denom * 8.0f;
            int bi = (int)tt;
            if (bi > 7) bi = 7;
            const ull one = 1ull << ((bi & 3) << 4);
            if (bi < 4) h0 += one; else h1 += one;
        }
        #pragma unroll
        for (int o = 16; o > 0; o >>= 1) {
            h0 += __shfl_xor_sync(0xffffffffu, h0, o);
            h1 += __shfl_xor_sync(0xffffffffu, h1, o);
        }
        if (lane == 0) { s_h[wid][0] = h0; s_h[wid][1] = h1; }
        __syncthreads();

        if (tid == 0) {
            ull H0 = 0ull, H1 = 0ull;
            #pragma unroll
            for (int w = 0; w < 16; w++) { H0 += s_h[w][0]; H1 += s_h[w][1]; }
            float c[8];
            #pragma unroll
            for (int bn = 0; bn < 4; bn++) {
                c[bn]     = (float)((H0 >> (bn * 16)) & 0xFFFFull);
                c[bn + 4] = (float)((H1 >> (bn * 16)) & 0xFFFFull);
            }
            float ss = 0.0f;
            #pragma unroll
            for (int bn = 0; bn < 8; bn++) ss += c[bn] * c[bn];
            float nrm = fmaxf(sqrtf(ss), 1e-12f);
            float* o1 = out + (a * BSZ + b) * 16 + t * 8;
            float* o2 = out + (b * BSZ + a) * 16 + t * 8;
            #pragma unroll
            for (int bn = 0; bn < 8; bn++) {
                const float val = c[bn] / nrm;
                o1[bn] = val;
                o2[bn] = val;   // hist(a,b) == hist(b,a) by symmetry
            }
        }
        // s_mn/s_h reuse next task is safe: all threads passed the s_h
        // barrier above before any thread can write s_mn again (8 chunk
        // barriers intervene).
    }
}

extern "C" void kernel_launch(void* const* d_in, const int* in_sizes, int n_in,
                              void* d_out, int out_size) {
    const float* m1 = (const float*)d_in[0];
    const float* m2 = (const float*)d_in[1];
    float* out = (float*)d_out;

    split_transpose<<<dim3(BSZ, 8, 8), dim3(32, 8)>>>(m1, m2);

    cudaFuncSetAttribute(pair_hmma,
                         cudaFuncAttributeMaxDynamicSharedMemorySize,
                         STAGES * STAGE_B);
    pair_hmma<<<GRID, 512, STAGES * STAGE_B>>>(out);
}

// round 9
// speedup vs baseline: 1.6918x; 1.4414x over previous
#include <cuda_runtime.h>
#include <cuda_fp16.h>
#include <cstdint>
#include <math.h>

#define BSZ    64
#define FDIM   256
#define MDIM   128
#define NPAIRS 2080            // 64*65/2 triangular pairs
#define KC     32              // K per chunk
#define NCH    (FDIM / KC)     // 8
#define TILE_B 8192            // 128 rows x 64B (32 fp16)
#define STAGE_B (4 * TILE_B)   // Ah, Al, Bh, Bl = 32KB
#define STAGES 3
#define LO_OFF (BSZ * MDIM * FDIM)   // elements between hi and lo planes
typedef unsigned long long ull;

// fp16 split scratch: [tensor][hi/lo][b][m][f], f contiguous = 16 MB
__device__ __align__(16) __half XS[2][2][BSZ][MDIM][FDIM];

// ---------------- pre-pass: transpose + fp16 hi/lo split ----------------
__global__ void split_transpose(const float* __restrict__ m1,
                                const float* __restrict__ m2) {
    __shared__ float tile[32][33];
    const int b  = blockIdx.x;
    const int f0 = blockIdx.y * 32;
    const int mt = blockIdx.z & 3, t = blockIdx.z >> 2;
    const int m0 = mt * 32;
    const float* src = t ? m2 : m1;
    const int tx = threadIdx.x, ty = threadIdx.y;
    #pragma unroll
    for (int i = 0; i < 4; i++) {
        int f = f0 + ty + i * 8;
        tile[ty + i * 8][tx] = src[((size_t)b * FDIM + f) * MDIM + m0 + tx];
    }
    __syncthreads();
    #pragma unroll
    for (int i = 0; i < 4; i++) {
        int m = m0 + ty + i * 8;
        int f = f0 + tx;
        float v = tile[tx][ty + i * 8];
        __half hi = __float2half_rn(v);
        __half lo = __float2half_rn(v - __half2float(hi));
        XS[t][0][b][m][f] = hi;
        XS[t][1][b][m][f] = lo;
    }
}

// ---------------- helpers ----------------
__device__ __forceinline__ uint32_t s2u(const void* p) {
    uint32_t a;
    asm("{ .reg .u64 t; cvta.to.shared.u64 t, %1; cvt.u32.u64 %0, t; }"
        : "=r"(a) : "l"(p));
    return a;
}
__device__ __forceinline__ void cpasync16(uint32_t dst, const void* src) {
    asm volatile("cp.async.cg.shared.global [%0], [%1], 16;"
                 :: "r"(dst), "l"(src));
}
template <int N>
__device__ __forceinline__ void cp_wait() {
    asm volatile("cp.async.wait_group %0;" :: "n"(N) : "memory");
}
__device__ __forceinline__ void ldsm4(uint32_t* r, uint32_t addr) {
    asm volatile("ldmatrix.sync.aligned.m8n8.x4.shared.b16 {%0,%1,%2,%3}, [%4];"
                 : "=r"(r[0]), "=r"(r[1]), "=r"(r[2]), "=r"(r[3]) : "r"(addr));
}
__device__ __forceinline__ void mma16816(float* c, const uint32_t* a,
                                         const uint32_t* b) {
    asm volatile(
        "mma.sync.aligned.m16n8k16.row.col.f32.f16.f16.f32 "
        "{%0,%1,%2,%3}, {%4,%5,%6,%7}, {%8,%9}, {%0,%1,%2,%3};"
        : "+f"(c[0]), "+f"(c[1]), "+f"(c[2]), "+f"(c[3])
        : "r"(a[0]), "r"(a[1]), "r"(a[2]), "r"(a[3]), "r"(b[0]), "r"(b[1]));
}
// swizzled byte offset of (row r, 16B-chunk j) inside a [128][64B] tile
__device__ __forceinline__ uint32_t swz(int r, int j) {
    return (uint32_t)(r * 64 + ((j ^ ((r >> 1) & 3)) << 4));
}

// ---------------- main kernel ----------------
__global__ __launch_bounds__(512, 2)
void pair_hmma(float* __restrict__ out) {
    extern __shared__ char dsm[];
    __shared__ float s_mn[16], s_mx[16];
    __shared__ ull   s_h[16][2];

    const int tid  = threadIdx.x;
    const int lane = tid & 31;
    const int wid  = tid >> 5;          // 0..15
    const int t    = blockIdx.y;

    // decode triangular pair p -> (a, b), a <= b
    int p = blockIdx.x;
    int b = (int)floorf((sqrtf(8.0f * (float)p + 1.0f) - 1.0f) * 0.5f);
    while ((b + 1) * (b + 2) / 2 <= p) ++b;
    while (b * (b + 1) / 2 > p) --b;
    const int a = p - b * (b + 1) / 2;

    const uint32_t sbase = s2u(dsm);
    const int m_base = (wid >> 2) * 32;
    const int n_base = (wid & 3) * 32;

    // hoisted ldmatrix offsets (chunk-invariant): [mt/t2][ks]
    uint32_t off_a[2][2], off_b[2][2];
    #pragma unroll
    for (int ks = 0; ks < 2; ks++) {
        #pragma unroll
        for (int mt = 0; mt < 2; mt++)
            off_a[mt][ks] = swz(m_base + mt * 16 + (lane & 15),
                                ks * 2 + (lane >> 4));
        #pragma unroll
        for (int t2 = 0; t2 < 2; t2++)
            off_b[t2][ks] = swz(n_base + t2 * 16 + ((lane >> 4) << 3) + (lane & 7),
                                ks * 2 + ((lane >> 3) & 1));
    }

    float acc[2][4][4];
    #pragma unroll
    for (int i = 0; i < 2; i++)
        #pragma unroll
        for (int j = 0; j < 4; j++)
            #pragma unroll
            for (int k = 0; k < 4; k++) acc[i][j][k] = 0.0f;

    // --- per-thread fixed cp.async slot: tile, row r, chunk j ---
    const int pr = tid >> 2;            // 0..127
    const int pj = tid & 3;             // 0..3
    const uint32_t pdst = swz(pr, pj);  // dst offset within a tile
    const __half* pAh = &XS[t][0][a][pr][pj * 8];
    const long dB = (long)(b - a) * (MDIM * FDIM);   // hi(a) -> hi(b)

    auto prefetch = [&](int ch) {
        const uint32_t stg = sbase + (uint32_t)(ch % STAGES) * STAGE_B;
        const __half* base = pAh + ch * KC;
        cpasync16(stg + pdst,              base);
        cpasync16(stg + TILE_B + pdst,     base + LO_OFF);
        cpasync16(stg + 2 * TILE_B + pdst, base + dB);
        cpasync16(stg + 3 * TILE_B + pdst, base + dB + LO_OFF);
        asm volatile("cp.async.commit_group;" ::: "memory");
    };

    prefetch(0);
    prefetch(1);

    #pragma unroll
    for (int ch = 0; ch < NCH; ch++) {
        if (ch < NCH - 1) cp_wait<1>(); else cp_wait<0>();
        __syncthreads();
        if (ch + 2 < NCH) prefetch(ch + 2);

        const uint32_t aH = sbase + (uint32_t)(ch % STAGES) * STAGE_B;
        const uint32_t aL = aH + TILE_B;
        const uint32_t bH = aH + 2 * TILE_B;
        const uint32_t bL = aH + 3 * TILE_B;

        #pragma unroll
        for (int ks = 0; ks < 2; ks++) {
            uint32_t ah[2][4], al[2][4];
            #pragma unroll
            for (int mt = 0; mt < 2; mt++) {
                ldsm4(ah[mt], aH + off_a[mt][ks]);
                ldsm4(al[mt], aL + off_a[mt][ks]);
            }
            #pragma unroll
            for (int t2 = 0; t2 < 2; t2++) {
                uint32_t bh[4], bl[4];
                ldsm4(bh, bH + off_b[t2][ks]);
                ldsm4(bl, bL + off_b[t2][ks]);
                #pragma unroll
                for (int mt = 0; mt < 2; mt++)
                    #pragma unroll
                    for (int n2 = 0; n2 < 2; n2++) {
                        float* c = acc[mt][t2 * 2 + n2];
                        mma16816(c, ah[mt], &bh[n2 * 2]);
                        mma16816(c, ah[mt], &bl[n2 * 2]);
                        mma16816(c, al[mt], &bh[n2 * 2]);
                    }
            }
        }
    }

    // -------- epilogue: min/max + histogram over all 16384 CTA values --------
    const float* va = &acc[0][0][0];
    float mn = va[0], mx = va[0];
    #pragma unroll
    for (int q = 1; q < 32; q++) { mn = fminf(mn, va[q]); mx = fmaxf(mx, va[q]); }
    #pragma unroll
    for (int o = 16; o > 0; o >>= 1) {
        mn = fminf(mn, __shfl_xor_sync(0xffffffffu, mn, o));
        mx = fmaxf(mx, __shfl_xor_sync(0xffffffffu, mx, o));
    }
    if (lane == 0) { s_mn[wid] = mn; s_mx[wid] = mx; }
    __syncthreads();
    mn = s_mn[0]; mx = s_mx[0];
    #pragma unroll
    for (int w = 1; w < 16; w++) {
        mn = fminf(mn, s_mn[w]); mx = fmaxf(mx, s_mx[w]);
    }
    const float denom = (mx > mn) ? (mx - mn) : 1.0f;
    const float invd  = 8.0f / denom;          // one division per task

    // per-thread histogram: 8 bins x 8-bit fields in one u64 (max 32/field)
    ull h = 0ull;
    #pragma unroll
    for (int q = 0; q < 32; q++) {
        const float tt = (va[q] - mn) * invd;
        int bi = (int)tt;                      // tt >= 0 -> trunc == floor
        if (bi > 7) bi = 7;
        h += 1ull << (bi << 3);
    }
    // expand 8x8-bit -> 2 x (4x16-bit) for overflow-safe warp/CTA reduce
    const uint32_t lo32 = (uint32_t)h, hi32 = (uint32_t)(h >> 32);
    ull h0 = (ull)__byte_perm(lo32, 0, 0x4140) |
             ((ull)__byte_perm(lo32, 0, 0x4342) << 32);
    ull h1 = (ull)__byte_perm(hi32, 0, 0x4140) |
             ((ull)__byte_perm(hi32, 0, 0x4342) << 32);
    #pragma unroll
    for (int o = 16; o > 0; o >>= 1) {
        h0 += __shfl_xor_sync(0xffffffffu, h0, o);
        h1 += __shfl_xor_sync(0xffffffffu, h1, o);
    }
    if (lane == 0) { s_h[wid][0] = h0; s_h[wid][1] = h1; }
    __syncthreads();

    if (tid == 0) {
        ull H0 = 0ull, H1 = 0ull;
        #pragma unroll
        for (int w = 0; w < 16; w++) { H0 += s_h[w][0]; H1 += s_h[w][1]; }
        float c[8];
        #pragma unroll
        for (int bn = 0; bn < 4; bn++) {
            c[bn]     = (float)((H0 >> (bn * 16)) & 0xFFFFull);
            c[bn + 4] = (float)((H1 >> (bn * 16)) & 0xFFFFull);
        }
        float ss = 0.0f;
        #pragma unroll
        for (int bn = 0; bn < 8; bn++) ss += c[bn] * c[bn];
        float nrm = fmaxf(sqrtf(ss), 1e-12f);
        float* o1 = out + (a * BSZ + b) * 16 + t * 8;
        float* o2 = out + (b * BSZ + a) * 16 + t * 8;
        #pragma unroll
        for (int bn = 0; bn < 8; bn++) {
            const float val = c[bn] / nrm;
            o1[bn] = val;
            o2[bn] = val;   // hist(a,b) == hist(b,a) by symmetry
        }
    }
}

extern "C" void kernel_launch(void* const* d_in, const int* in_sizes, int n_in,
                              void* d_out, int out_size) {
    const float* m1 = (const float*)d_in[0];
    const float* m2 = (const float*)d_in[1];
    float* out = (float*)d_out;

    split_transpose<<<dim3(BSZ, 8, 8), dim3(32, 8)>>>(m1, m2);

    cudaFuncSetAttribute(pair_hmma,
                         cudaFuncAttributeMaxDynamicSharedMemorySize,
                         STAGES * STAGE_B);
    pair_hmma<<<dim3(NPAIRS, 2), 512, STAGES * STAGE_B>>>(out);
}